// round 1
// baseline (speedup 1.0000x reference)
#include <cuda_runtime.h>
#include <math.h>

#define NN 100000
#define EE 1600000
#define C 64

// ---------------- device scratch (static, allocation-free) ----------------
__device__ float g_asrc[NN * C];
__device__ float g_adst[NN * C];
__device__ float g_v[NN * C];
__device__ float g_num[NN * C];
__device__ float g_den[NN * C];

// ---------------- helpers ----------------
__device__ __forceinline__ void red_add4(float* p, float4 v) {
    asm volatile("red.global.add.v4.f32 [%0], {%1,%2,%3,%4};"
                 :: "l"(p), "f"(v.x), "f"(v.y), "f"(v.z), "f"(v.w)
                 : "memory");
}

__device__ __forceinline__ float4 f4fma(float s, float4 w, float4 a) {
    a.x = fmaf(s, w.x, a.x);
    a.y = fmaf(s, w.y, a.y);
    a.z = fmaf(s, w.z, a.z);
    a.w = fmaf(s, w.w, a.w);
    return a;
}
__device__ __forceinline__ float4 f4relu(float4 a) {
    a.x = fmaxf(a.x, 0.f); a.y = fmaxf(a.y, 0.f);
    a.z = fmaxf(a.z, 0.f); a.w = fmaxf(a.w, 0.f);
    return a;
}

// ---------------- init ----------------
__global__ void zero_kernel() {
    int i = blockIdx.x * blockDim.x + threadIdx.x;
    int stride = gridDim.x * blockDim.x;
    float4 z = make_float4(0.f, 0.f, 0.f, 0.f);
    for (; i < NN * C / 4; i += stride) {
        ((float4*)g_num)[i] = z;
        ((float4*)g_den)[i] = z;
    }
}

// ---------------- node prep: h = relu(x@W_in+b); asrc/adst/v = h@{W_src,W_dst,W_lin} ----------------
// blockDim (16,16): tx -> 4 channels (c0 = tx*4), ty -> node slot
__global__ void __launch_bounds__(256) node_prep(
    const float* __restrict__ x,
    const float* __restrict__ W_in, const float* __restrict__ b_in,
    const float* __restrict__ W_lin, const float* __restrict__ W_src,
    const float* __restrict__ W_dst)
{
    extern __shared__ float sm[];
    float* sWin = sm;            // 4096
    float* sbin = sm + 4096;     // 64
    float* sWs  = sm + 4160;     // 4096
    float* sWd  = sm + 8256;     // 4096
    float* sWl  = sm + 12352;    // 4096
    float* sx   = sm + 16448;    // 16*64
    float* sh   = sm + 17472;    // 16*64  (total 18496 floats)

    int t = threadIdx.y * 16 + threadIdx.x;
    for (int i = t; i < 4096; i += 256) {
        sWin[i] = W_in[i];
        sWs[i]  = W_src[i];
        sWd[i]  = W_dst[i];
        sWl[i]  = W_lin[i];
    }
    if (t < 64) sbin[t] = b_in[t];
    __syncthreads();

    int tx = threadIdx.x, ty = threadIdx.y;
    int c0 = tx * 4;
    int ntiles = (NN + 15) / 16;
    for (int tile = blockIdx.x; tile < ntiles; tile += gridDim.x) {
        int n = tile * 16 + ty;
        bool valid = (n < NN);
        if (valid) {
            *(float4*)&sx[ty * 64 + c0] = *(const float4*)&x[(long)n * 64 + c0];
        }
        __syncwarp();
        if (valid) {
            float4 acc = *(float4*)&sbin[c0];
#pragma unroll
            for (int k = 0; k < 64; k++) {
                float xk = sx[ty * 64 + k];
                acc = f4fma(xk, *(float4*)&sWin[k * 64 + c0], acc);
            }
            *(float4*)&sh[ty * 64 + c0] = f4relu(acc);
        }
        __syncwarp();
        if (valid) {
            float4 a0 = make_float4(0, 0, 0, 0);
            float4 a1 = make_float4(0, 0, 0, 0);
            float4 a2 = make_float4(0, 0, 0, 0);
#pragma unroll
            for (int k = 0; k < 64; k++) {
                float hk = sh[ty * 64 + k];
                a0 = f4fma(hk, *(float4*)&sWs[k * 64 + c0], a0);
                a1 = f4fma(hk, *(float4*)&sWd[k * 64 + c0], a1);
                a2 = f4fma(hk, *(float4*)&sWl[k * 64 + c0], a2);
            }
            *(float4*)&g_asrc[(long)n * 64 + c0] = a0;
            *(float4*)&g_adst[(long)n * 64 + c0] = a1;
            *(float4*)&g_v[(long)n * 64 + c0]    = a2;
        }
        __syncwarp();
    }
}

// ---------------- edge kernel: fused pos-MLP + attn-MLP + softmax-accumulate ----------------
// blockDim (16,16): tx -> 4 channels, ty -> edge slot
__global__ void __launch_bounds__(256) edge_kernel(
    const float* __restrict__ pos,
    const int* __restrict__ src, const int* __restrict__ dst,
    const float* __restrict__ posw1, const float* __restrict__ posb1,
    const float* __restrict__ posw2, const float* __restrict__ posb2,
    const float* __restrict__ attw1, const float* __restrict__ attb1,
    const float* __restrict__ attw2, const float* __restrict__ attb2)
{
    extern __shared__ float sm[];
    float* sw1  = sm;            // 192
    float* sb1  = sm + 192;      // 64
    float* sw2  = sm + 256;      // 4096
    float* sb2  = sm + 4352;     // 64
    float* sa1  = sm + 4416;     // 4096
    float* sab1 = sm + 8512;     // 64
    float* sa2  = sm + 8576;     // 4096
    float* sab2 = sm + 12672;    // 64
    float* shid = sm + 12736;    // 16*64
    float* st   = sm + 13760;    // 16*64   (total 14784 floats)

    int t = threadIdx.y * 16 + threadIdx.x;
    for (int i = t; i < 4096; i += 256) {
        sw2[i] = posw2[i];
        sa1[i] = attw1[i];
        sa2[i] = attw2[i];
    }
    if (t < 192) sw1[t] = posw1[t];
    if (t < 64) {
        sb1[t]  = posb1[t];
        sb2[t]  = posb2[t];
        sab1[t] = attb1[t];
        sab2[t] = attb2[t];
    }
    __syncthreads();

    int tx = threadIdx.x, ty = threadIdx.y;
    int c0 = tx * 4;
    int ntiles = (EE + 15) / 16;
    for (int tile = blockIdx.x; tile < ntiles; tile += gridDim.x) {
        int e = tile * 16 + ty;
        bool valid = (e < EE);
        int s_ = 0, d_ = 0;
        float4 del = make_float4(0, 0, 0, 0);

        if (valid) {
            s_ = src[e];
            d_ = dst[e];
            float p0 = pos[d_ * 3 + 0] - pos[s_ * 3 + 0];
            float p1 = pos[d_ * 3 + 1] - pos[s_ * 3 + 1];
            float p2 = pos[d_ * 3 + 2] - pos[s_ * 3 + 2];
            float4 acc = *(float4*)&sb1[c0];
            acc = f4fma(p0, *(float4*)&sw1[0 * 64 + c0], acc);
            acc = f4fma(p1, *(float4*)&sw1[1 * 64 + c0], acc);
            acc = f4fma(p2, *(float4*)&sw1[2 * 64 + c0], acc);
            *(float4*)&shid[ty * 64 + c0] = f4relu(acc);
        }
        __syncwarp();
        if (valid) {
            float4 acc = *(float4*)&sb2[c0];
#pragma unroll
            for (int k = 0; k < 64; k++) {
                float hk = shid[ty * 64 + k];
                acc = f4fma(hk, *(float4*)&sw2[k * 64 + c0], acc);
            }
            del = f4relu(acc);  // delta, kept in registers for the numerator
            float4 ad = *(const float4*)&g_adst[(long)d_ * 64 + c0];
            float4 as = *(const float4*)&g_asrc[(long)s_ * 64 + c0];
            float4 tv;
            tv.x = ad.x - as.x + del.x;
            tv.y = ad.y - as.y + del.y;
            tv.z = ad.z - as.z + del.z;
            tv.w = ad.w - as.w + del.w;
            *(float4*)&st[ty * 64 + c0] = tv;
        }
        __syncwarp();
        if (valid) {
            float4 acc = *(float4*)&sab1[c0];
#pragma unroll
            for (int k = 0; k < 64; k++) {
                float tk = st[ty * 64 + k];
                acc = f4fma(tk, *(float4*)&sa1[k * 64 + c0], acc);
            }
            *(float4*)&shid[ty * 64 + c0] = f4relu(acc);
        }
        __syncwarp();
        if (valid) {
            float4 acc = *(float4*)&sab2[c0];
#pragma unroll
            for (int k = 0; k < 64; k++) {
                float hk = shid[ty * 64 + k];
                acc = f4fma(hk, *(float4*)&sa2[k * 64 + c0], acc);
            }
            float4 a = f4relu(acc);
            float4 ex;
            ex.x = expf(a.x); ex.y = expf(a.y);
            ex.z = expf(a.z); ex.w = expf(a.w);
            float4 vv = *(const float4*)&g_v[(long)s_ * 64 + c0];
            float4 m;
            m.x = ex.x * (vv.x + del.x);
            m.y = ex.y * (vv.y + del.y);
            m.z = ex.z * (vv.z + del.z);
            m.w = ex.w * (vv.w + del.w);
            red_add4(&g_num[(long)d_ * 64 + c0], m);
            red_add4(&g_den[(long)d_ * 64 + c0], ex);
        }
        __syncwarp();
    }
}

// ---------------- final: out = relu((num/den)@W_out + b_out) ----------------
__global__ void __launch_bounds__(256) final_kernel(
    const float* __restrict__ W_out, const float* __restrict__ b_out,
    float* __restrict__ out)
{
    __shared__ float sW[4096];
    __shared__ float sb[64];
    __shared__ float sr[16 * 64];

    int t = threadIdx.y * 16 + threadIdx.x;
    for (int i = t; i < 4096; i += 256) sW[i] = W_out[i];
    if (t < 64) sb[t] = b_out[t];
    __syncthreads();

    int tx = threadIdx.x, ty = threadIdx.y;
    int c0 = tx * 4;
    int ntiles = (NN + 15) / 16;
    for (int tile = blockIdx.x; tile < ntiles; tile += gridDim.x) {
        int n = tile * 16 + ty;
        bool valid = (n < NN);
        if (valid) {
            float4 nu = *(const float4*)&g_num[(long)n * 64 + c0];
            float4 de = *(const float4*)&g_den[(long)n * 64 + c0];
            float4 r;
            r.x = nu.x / (de.x + 1e-16f);
            r.y = nu.y / (de.y + 1e-16f);
            r.z = nu.z / (de.z + 1e-16f);
            r.w = nu.w / (de.w + 1e-16f);
            *(float4*)&sr[ty * 64 + c0] = r;
        }
        __syncwarp();
        if (valid) {
            float4 acc = *(float4*)&sb[c0];
#pragma unroll
            for (int k = 0; k < 64; k++) {
                float rk = sr[ty * 64 + k];
                acc = f4fma(rk, *(float4*)&sW[k * 64 + c0], acc);
            }
            *(float4*)&out[(long)n * 64 + c0] = f4relu(acc);
        }
        __syncwarp();
    }
}

// ---------------- launch ----------------
extern "C" void kernel_launch(void* const* d_in, const int* in_sizes, int n_in,
                              void* d_out, int out_size)
{
    const float* x      = (const float*)d_in[0];
    const float* pos    = (const float*)d_in[1];
    const int*   ei     = (const int*)d_in[2];   // [2, E] int32: row0 = src, row1 = dst
    const float* W_in   = (const float*)d_in[3];
    const float* b_in   = (const float*)d_in[4];
    const float* W_out  = (const float*)d_in[5];
    const float* b_out  = (const float*)d_in[6];
    const float* W_lin  = (const float*)d_in[7];
    const float* W_src  = (const float*)d_in[8];
    const float* W_dst  = (const float*)d_in[9];
    const float* posw1  = (const float*)d_in[10];
    const float* posb1  = (const float*)d_in[11];
    const float* posw2  = (const float*)d_in[12];
    const float* posb2  = (const float*)d_in[13];
    const float* attw1  = (const float*)d_in[14];
    const float* attb1  = (const float*)d_in[15];
    const float* attw2  = (const float*)d_in[16];
    const float* attb2  = (const float*)d_in[17];
    float* out = (float*)d_out;

    const int NP_SMEM = 18496 * 4;  // 73984 B
    const int EK_SMEM = 14784 * 4;  // 59136 B
    cudaFuncSetAttribute(node_prep, cudaFuncAttributeMaxDynamicSharedMemorySize, NP_SMEM);
    cudaFuncSetAttribute(edge_kernel, cudaFuncAttributeMaxDynamicSharedMemorySize, EK_SMEM);

    zero_kernel<<<1024, 256>>>();
    node_prep<<<444, dim3(16, 16), NP_SMEM>>>(x, W_in, b_in, W_lin, W_src, W_dst);
    edge_kernel<<<888, dim3(16, 16), EK_SMEM>>>(pos, ei, ei + EE,
                                                posw1, posb1, posw2, posb2,
                                                attw1, attb1, attw2, attb2);
    final_kernel<<<444, dim3(16, 16)>>>(W_out, b_out, out);
}